// round 3
// baseline (speedup 1.0000x reference)
#include <cuda_runtime.h>
#include <cuda_bf16.h>

// AUCM loss, single fused kernel.
// loss = [ sum_{i in P, j in N} (1 - p_i + n_j)^2 + relu(1 - p_i + n_j) ] / (|P||N|)
// Quadratic term has closed form from per-class sums (block 0 computes it);
// only the relu term needs the pairwise loop.

#define THREADS 256
#define NBLOCKS 148
#define PS      8        // positive-list slices per element
#define MAXPOS  4096     // ~1200 positives expected; ample margin

__device__ double g_partials[NBLOCKS];
__device__ int    g_done = 0;   // reset by last block each run

// Tree reduce a double across the block; result valid in thread 0.
__device__ __forceinline__ double block_reduce(double v, double* s_w) {
    int lane = threadIdx.x & 31, wid = threadIdx.x >> 5;
    #pragma unroll
    for (int o = 16; o; o >>= 1) v += __shfl_down_sync(0xffffffffu, v, o);
    if (lane == 0) s_w[wid] = v;
    __syncthreads();
    double r = 0.0;
    if (wid == 0) {
        r = (lane < THREADS / 32) ? s_w[lane] : 0.0;
        #pragma unroll
        for (int o = 4; o; o >>= 1) r += __shfl_down_sync(0xffffffffu, r, o);
    }
    __syncthreads();  // s_w reusable after return
    return r;
}

__global__ void __launch_bounds__(THREADS)
aucm_fused_kernel(const float* __restrict__ preds,
                  const int* __restrict__ targets,
                  int n, float* __restrict__ out, int out_size) {
    __shared__ float  s_pos[MAXPOS];
    __shared__ int    s_cnt;
    __shared__ int    s_last;
    __shared__ double s_w[THREADS / 32];

    const int tid  = threadIdx.x;
    const int bid  = blockIdx.x;
    const int lane = tid & 31;
    const unsigned lt_mask = (1u << lane) - 1u;
    const bool isB0 = (bid == 0);

    if (tid == 0) { s_cnt = 0; s_last = 0; }
    __syncthreads();

    // ---- Phase 1: compact positives into shared (all blocks, redundant).
    //      Block 0 additionally accumulates class sums for the closed form.
    float sa = 0.f, sa2 = 0.f, sn = 0.f, sn2 = 0.f;
    for (int i0 = 0; i0 < n; i0 += THREADS) {
        int i = i0 + tid;
        bool inb = (i < n);
        int  t   = inb ? targets[i] : 0;
        bool isP = inb && (t == 1);
        float v = 0.f;
        if (isB0) {
            if (inb) {
                v = preds[i];
                if (isP) { float a = 1.f - v; sa += a; sa2 += a * a; }
                else     { sn += v; sn2 += v * v; }
            }
        } else if (isP) {
            v = preds[i];
        }
        unsigned m = __ballot_sync(0xffffffffu, isP);
        int cnt = __popc(m);
        int base = 0;
        if (lane == 0 && cnt) base = atomicAdd(&s_cnt, cnt);
        base = __shfl_sync(0xffffffffu, base, 0);
        if (isP) {
            int idx = base + __popc(m & lt_mask);
            if (idx < MAXPOS) s_pos[idx] = v;
        }
    }
    __syncthreads();
    const int pcount = s_cnt;

    // ---- Phase 2: relu term. Units = (element, slice), elem-major so warp
    //      lanes share a slice -> s_pos reads broadcast.
    const int per = (pcount + PS - 1) / PS;
    const int gtid = bid * THREADS + tid;
    const int nthreads = NBLOCKS * THREADS;
    double dacc = 0.0;
    for (int u = gtid; u < PS * n; u += nthreads) {
        int slice = u / n;
        int i = u - slice * n;
        if (targets[i] != 0) continue;       // negatives only
        float c = 1.0f + preds[i];           // d = c - p
        int p0 = slice * per;
        int p1 = min(p0 + per, pcount);
        float a0 = 0.f, a1 = 0.f, a2 = 0.f, a3 = 0.f;
        float a4 = 0.f, a5 = 0.f, a6 = 0.f, a7 = 0.f;
        int k = p0;
        for (; k + 8 <= p1; k += 8) {
            a0 += fmaxf(c - s_pos[k],     0.f);
            a1 += fmaxf(c - s_pos[k + 1], 0.f);
            a2 += fmaxf(c - s_pos[k + 2], 0.f);
            a3 += fmaxf(c - s_pos[k + 3], 0.f);
            a4 += fmaxf(c - s_pos[k + 4], 0.f);
            a5 += fmaxf(c - s_pos[k + 5], 0.f);
            a6 += fmaxf(c - s_pos[k + 6], 0.f);
            a7 += fmaxf(c - s_pos[k + 7], 0.f);
        }
        for (; k < p1; k++) a0 += fmaxf(c - s_pos[k], 0.f);
        dacc += (double)(((a0 + a1) + (a2 + a3)) + ((a4 + a5) + (a6 + a7)));
    }

    // ---- Block reduce; block 0 adds the closed-form quadratic term.
    double bsum = block_reduce(dacc, s_w);
    if (isB0) {
        double dsa  = block_reduce((double)sa,  s_w);
        double dsa2 = block_reduce((double)sa2, s_w);
        double dsn  = block_reduce((double)sn,  s_w);
        double dsn2 = block_reduce((double)sn2, s_w);
        if (tid == 0) {
            double Np = (double)pcount, Nn = (double)(n - pcount);
            bsum += Nn * dsa2 + 2.0 * dsa * dsn + Np * dsn2;
        }
    }

    // ---- Last-block finalize (whole block participates in final reduce).
    if (tid == 0) {
        g_partials[bid] = bsum;
        __threadfence();
        int prev = atomicAdd(&g_done, 1);
        if (prev == NBLOCKS - 1) s_last = 1;
    }
    __syncthreads();
    if (s_last) {
        __threadfence();
        double v = (tid < NBLOCKS) ? g_partials[tid] : 0.0;
        double tot = block_reduce(v, s_w);
        if (tid == 0) {
            double denom = (double)pcount * (double)(n - pcount);
            float r = (float)(tot / denom);
            for (int j = 0; j < out_size; j++) out[j] = r;
            g_done = 0;   // restore invariant for next graph replay
        }
    }
}

extern "C" void kernel_launch(void* const* d_in, const int* in_sizes, int n_in,
                              void* d_out, int out_size) {
    const float* preds   = (const float*)d_in[0];
    const int*   targets = (const int*)d_in[1];
    int n = in_sizes[0];
    aucm_fused_kernel<<<NBLOCKS, THREADS>>>(preds, targets, n,
                                            (float*)d_out, out_size);
}

// round 4
// speedup vs baseline: 1.3750x; 1.3750x over previous
#include <cuda_runtime.h>
#include <cuda_bf16.h>

// AUCM loss, single fused kernel with software grid barrier (single wave).
// loss = [ sum_{i in P, j in N} (1-p_i+n_j)^2 + relu(1-p_i+n_j) ] / (|P||N|)
// Quadratic term closed form from S1,S2 (all elems) and Sp1,Sp2 (positives);
// only the relu term needs the pairwise loop.

#define THREADS 256
#define NBLOCKS 148
#define PS      8        // positive-list slices per element
#define MAXPOS  4096     // ~1200 positives expected; ample margin

__device__ float  g_pos[MAXPOS];
__device__ int    g_cnt    = 0;   // positives count   (reset at finalize)
__device__ int    g_arrive = 0;   // barrier counter   (reset at finalize)
__device__ int    g_done   = 0;   // finalize counter  (reset at finalize)
__device__ double g_relu[NBLOCKS];
__device__ double g_s1[NBLOCKS];
__device__ double g_s2[NBLOCKS];

// Tree reduce a double across the block; result valid in thread 0.
__device__ __forceinline__ double block_reduce(double v, double* s_w) {
    int lane = threadIdx.x & 31, wid = threadIdx.x >> 5;
    #pragma unroll
    for (int o = 16; o; o >>= 1) v += __shfl_down_sync(0xffffffffu, v, o);
    if (lane == 0) s_w[wid] = v;
    __syncthreads();
    double r = 0.0;
    if (wid == 0) {
        r = (lane < THREADS / 32) ? s_w[lane] : 0.0;
        #pragma unroll
        for (int o = 4; o; o >>= 1) r += __shfl_down_sync(0xffffffffu, r, o);
    }
    __syncthreads();  // s_w reusable after return
    return r;
}

__global__ void __launch_bounds__(THREADS)
aucm_fused_kernel(const float* __restrict__ preds,
                  const int* __restrict__ targets,
                  int n, float* __restrict__ out, int out_size) {
    __shared__ float  s_pos[MAXPOS];
    __shared__ int    s_last;
    __shared__ double s_w[THREADS / 32];

    const int tid  = threadIdx.x;
    const int bid  = blockIdx.x;
    const int lane = tid & 31;
    const unsigned lt_mask = (1u << lane) - 1u;
    const int gtid = bid * THREADS + tid;
    const int nthreads = NBLOCKS * THREADS;

    if (tid == 0) s_last = 0;

    // ---- Phase A: one pass over the data, distributed across the grid.
    //      Compact positives into global g_pos; accumulate S1, S2 partials.
    double s1 = 0.0, s2 = 0.0;
    for (int i = gtid; i < n; i += nthreads) {   // 1 iteration for n<=37888
        int   t = targets[i];
        float v = preds[i];
        s1 += (double)v;
        s2 += (double)v * (double)v;
        bool isP = (t == 1);
        unsigned m = __ballot_sync(0xffffffffu, isP);
        int cnt = __popc(m);
        int base = 0;
        if (lane == 0 && cnt) base = atomicAdd(&g_cnt, cnt);
        base = __shfl_sync(0xffffffffu, base, 0);
        if (isP) {
            int idx = base + __popc(m & lt_mask);
            if (idx < MAXPOS) g_pos[idx] = v;
        }
    }
    double bs1 = block_reduce(s1, s_w);
    double bs2 = block_reduce(s2, s_w);
    if (tid == 0) { g_s1[bid] = bs1; g_s2[bid] = bs2; }

    // ---- Grid barrier (all 148 blocks resident in one wave).
    __threadfence();                        // release g_pos / g_s* writes
    __syncthreads();                        // whole block has arrived
    if (tid == 0) {
        atomicAdd(&g_arrive, 1);
        while (*(volatile int*)&g_arrive < NBLOCKS) { }
    }
    __syncthreads();
    __threadfence();                        // acquire

    const int pcount = min(*(volatile int*)&g_cnt, MAXPOS);

    // Stage positives into shared.
    for (int k = tid; k < pcount; k += THREADS) s_pos[k] = g_pos[k];
    __syncthreads();

    // ---- Phase 2: relu term. Units = (element, slice), elem-major so warp
    //      lanes share a slice -> s_pos reads broadcast.
    const int per = (pcount + PS - 1) / PS;
    double dacc = 0.0;
    for (int u = gtid; u < PS * n; u += nthreads) {
        int slice = u / n;
        int i = u - slice * n;
        if (targets[i] != 0) continue;       // negatives only
        float c = 1.0f + preds[i];           // d = c - p
        int p0 = slice * per;
        int p1 = min(p0 + per, pcount);
        float a0 = 0.f, a1 = 0.f, a2 = 0.f, a3 = 0.f;
        float a4 = 0.f, a5 = 0.f, a6 = 0.f, a7 = 0.f;
        int k = p0;
        for (; k + 8 <= p1; k += 8) {
            a0 += fmaxf(c - s_pos[k],     0.f);
            a1 += fmaxf(c - s_pos[k + 1], 0.f);
            a2 += fmaxf(c - s_pos[k + 2], 0.f);
            a3 += fmaxf(c - s_pos[k + 3], 0.f);
            a4 += fmaxf(c - s_pos[k + 4], 0.f);
            a5 += fmaxf(c - s_pos[k + 5], 0.f);
            a6 += fmaxf(c - s_pos[k + 6], 0.f);
            a7 += fmaxf(c - s_pos[k + 7], 0.f);
        }
        for (; k < p1; k++) a0 += fmaxf(c - s_pos[k], 0.f);
        dacc += (double)(((a0 + a1) + (a2 + a3)) + ((a4 + a5) + (a6 + a7)));
    }
    double brelu = block_reduce(dacc, s_w);

    // ---- Publish per-block partial, elect last block.
    if (tid == 0) {
        g_relu[bid] = brelu;
        __threadfence();
        int prev = atomicAdd(&g_done, 1);
        if (prev == NBLOCKS - 1) s_last = 1;
    }
    __syncthreads();

    // ---- Last-block finalize.
    if (s_last) {
        __threadfence();
        double vr = (tid < NBLOCKS) ? g_relu[tid] : 0.0;
        double v1 = (tid < NBLOCKS) ? g_s1[tid]   : 0.0;
        double v2 = (tid < NBLOCKS) ? g_s2[tid]   : 0.0;
        double relu_sum = block_reduce(vr, s_w);
        double S1 = block_reduce(v1, s_w);
        double S2 = block_reduce(v2, s_w);

        // Sp1, Sp2 over positives from shared copy.
        double sp1 = 0.0, sp2 = 0.0;
        for (int k = tid; k < pcount; k += THREADS) {
            double p = (double)s_pos[k];
            sp1 += p; sp2 += p * p;
        }
        double Sp1 = block_reduce(sp1, s_w);
        double Sp2 = block_reduce(sp2, s_w);

        if (tid == 0) {
            double Np = (double)pcount, Nn = (double)(n - pcount);
            double sa  = Np - Sp1;
            double sa2 = Np - 2.0 * Sp1 + Sp2;
            double sn  = S1 - Sp1;
            double sn2 = S2 - Sp2;
            double quad = Nn * sa2 + 2.0 * sa * sn + Np * sn2;
            double total = relu_sum + quad;
            float r = (float)(total / (Np * Nn));
            for (int j = 0; j < out_size; j++) out[j] = r;
            // Restore invariants for next graph replay.
            g_cnt = 0; g_arrive = 0; g_done = 0;
        }
    }
}

extern "C" void kernel_launch(void* const* d_in, const int* in_sizes, int n_in,
                              void* d_out, int out_size) {
    const float* preds   = (const float*)d_in[0];
    const int*   targets = (const int*)d_in[1];
    int n = in_sizes[0];
    aucm_fused_kernel<<<NBLOCKS, THREADS>>>(preds, targets, n,
                                            (float*)d_out, out_size);
}

// round 6
// speedup vs baseline: 1.6370x; 1.1905x over previous
#include <cuda_runtime.h>
#include <cuda_bf16.h>

// AUCM loss, single fused kernel, software grid barrier (single wave).
// loss = [ sum_{P x N} (1-p+n)^2 + relu(1-p+n) ] / (|P||N|)
// Quadratic term in closed form; relu term pairwise with positives held in
// REGISTERS (PVEC per thread) and negatives streamed via broadcast LDS.

#define THREADS 512
#define NBLOCKS 148
#define PVEC    5              // positives per thread-group slot
#define PGROUPS 256            // thread-groups per block (tid & 255)
#define MAXPOS  4096
#define MAXN    16384
#define PADV    1.0e30f        // padded positive -> relu term 0

__device__ float  g_pos[MAXPOS];
__device__ float  g_neg[MAXN];
__device__ int    g_cnt    = 0;   // positives counter
__device__ int    g_ncnt   = 0;   // negatives counter
__device__ int    g_arrive = 0;   // grid barrier
__device__ int    g_done   = 0;   // finalize election
__device__ double g_relu[NBLOCKS];
__device__ double g_s1[NBLOCKS];
__device__ double g_s2[NBLOCKS];

__device__ __forceinline__ double block_reduce(double v, double* s_w) {
    int lane = threadIdx.x & 31, wid = threadIdx.x >> 5;
    #pragma unroll
    for (int o = 16; o; o >>= 1) v += __shfl_down_sync(0xffffffffu, v, o);
    if (lane == 0) s_w[wid] = v;
    __syncthreads();
    double r = 0.0;
    if (wid == 0) {
        r = (lane < THREADS / 32) ? s_w[lane] : 0.0;
        #pragma unroll
        for (int o = 8; o; o >>= 1) r += __shfl_down_sync(0xffffffffu, r, o);
    }
    __syncthreads();
    return r;
}

__global__ void __launch_bounds__(THREADS)
aucm_fused_kernel(const float* __restrict__ preds,
                  const int* __restrict__ targets,
                  int n, float* __restrict__ out, int out_size) {
    __shared__ float  s_neg[256];
    __shared__ int    s_last;
    __shared__ double s_w[THREADS / 32];

    const int tid  = threadIdx.x;
    const int bid  = blockIdx.x;
    const int lane = tid & 31;
    const unsigned lt_mask = (1u << lane) - 1u;
    const int gtid = bid * THREADS + tid;
    const int nthreads = NBLOCKS * THREADS;

    if (tid == 0) s_last = 0;

    // ---- Phase A: one pass; compact positives AND negatives to global,
    //      accumulate per-block S1, S2 over all elements.
    double s1 = 0.0, s2 = 0.0;
    for (int i = gtid; i < n; i += nthreads) {   // <=1 iter for n<=75776
        int   t = targets[i];
        float v = preds[i];
        s1 += (double)v;
        s2 += (double)v * (double)v;
        bool isP = (t == 1);
        unsigned mp = __ballot_sync(0xffffffffu, isP);
        unsigned mn = __ballot_sync(0xffffffffu, !isP);
        int basep = 0, basen = 0;
        if (lane == 0) {
            if (mp) basep = atomicAdd(&g_cnt,  __popc(mp));
            if (mn) basen = atomicAdd(&g_ncnt, __popc(mn));
        }
        basep = __shfl_sync(0xffffffffu, basep, 0);
        basen = __shfl_sync(0xffffffffu, basen, 0);
        if (isP) {
            int idx = basep + __popc(mp & lt_mask);
            if (idx < MAXPOS) g_pos[idx] = v;
        } else {
            int idx = basen + __popc(mn & lt_mask);
            g_neg[idx] = v;
        }
    }
    double bs1 = block_reduce(s1, s_w);
    double bs2 = block_reduce(s2, s_w);
    if (tid == 0) { g_s1[bid] = bs1; g_s2[bid] = bs2; }

    // ---- Grid barrier (148 blocks, all resident).
    __threadfence();
    __syncthreads();
    if (tid == 0) {
        atomicAdd(&g_arrive, 1);
        while (*(volatile int*)&g_arrive < NBLOCKS) { }
    }
    __syncthreads();
    __threadfence();

    const int pcount = min(*(volatile int*)&g_cnt, MAXPOS);
    const int ncount = *(volatile int*)&g_ncnt;

    // ---- Stage this block's negative chunk into shared.
    const int NC = (ncount + NBLOCKS - 1) / NBLOCKS;      // <=111 for n=16384
    const int j0 = bid * NC;
    const int j1 = min(j0 + NC, ncount);
    const int nc = j1 - j0;                               // this block's count
    for (int k = tid; k < nc; k += THREADS) s_neg[k] = g_neg[j0 + k];
    __syncthreads();

    // ---- Phase 2: relu term. Thread = (pgroup g, half h). Positives in regs.
    const int g = tid & (PGROUPS - 1);
    const int h = tid >> 8;                               // 0 or 1
    const int jh0 = h * (nc >> 1);
    const int jh1 = (h == 0) ? (nc >> 1) : nc;

    float facc = 0.0f;
    double dacc = 0.0;
    for (int gb = g; gb * PVEC < pcount; gb += PGROUPS) { // 1 iter if pcount<=1280
        float p0 = PADV, p1 = PADV, p2 = PADV, p3 = PADV, p4 = PADV;
        int pb = gb * PVEC;
        if (pb + 0 < pcount) p0 = g_pos[pb + 0];
        if (pb + 1 < pcount) p1 = g_pos[pb + 1];
        if (pb + 2 < pcount) p2 = g_pos[pb + 2];
        if (pb + 3 < pcount) p3 = g_pos[pb + 3];
        if (pb + 4 < pcount) p4 = g_pos[pb + 4];

        float a0 = 0.f, a1 = 0.f;
        for (int j = jh0; j < jh1; ++j) {
            float c = 1.0f + s_neg[j];        // broadcast LDS
            a0 += fmaxf(c - p0, 0.f);
            a1 += fmaxf(c - p1, 0.f);
            a0 += fmaxf(c - p2, 0.f);
            a1 += fmaxf(c - p3, 0.f);
            a0 += fmaxf(c - p4, 0.f);
        }
        facc = a0 + a1;
        dacc += (double)facc;
    }
    double brelu = block_reduce(dacc, s_w);

    // ---- Publish per-block partial, elect last block.
    if (tid == 0) {
        g_relu[bid] = brelu;
        __threadfence();
        int prev = atomicAdd(&g_done, 1);
        if (prev == NBLOCKS - 1) s_last = 1;
    }
    __syncthreads();

    // ---- Last-block finalize.
    if (s_last) {
        __threadfence();
        double vr = (tid < NBLOCKS) ? g_relu[tid] : 0.0;
        double v1 = (tid < NBLOCKS) ? g_s1[tid]   : 0.0;
        double v2 = (tid < NBLOCKS) ? g_s2[tid]   : 0.0;
        double relu_sum = block_reduce(vr, s_w);
        double S1 = block_reduce(v1, s_w);
        double S2 = block_reduce(v2, s_w);

        double sp1 = 0.0, sp2 = 0.0;
        for (int k = tid; k < pcount; k += THREADS) {
            double p = (double)g_pos[k];
            sp1 += p; sp2 += p * p;
        }
        double Sp1 = block_reduce(sp1, s_w);
        double Sp2 = block_reduce(sp2, s_w);

        if (tid == 0) {
            double Np = (double)pcount, Nn = (double)(n - pcount);
            double sa  = Np - Sp1;                    // sum (1-p)
            double sa2 = Np - 2.0 * Sp1 + Sp2;        // sum (1-p)^2
            double sn  = S1 - Sp1;                    // sum n
            double sn2 = S2 - Sp2;                    // sum n^2
            double quad = Nn * sa2 + 2.0 * sa * sn + Np * sn2;
            float r = (float)((relu_sum + quad) / (Np * Nn));
            for (int j = 0; j < out_size; j++) out[j] = r;
            g_cnt = 0; g_ncnt = 0; g_arrive = 0; g_done = 0;
        }
    }
}

extern "C" void kernel_launch(void* const* d_in, const int* in_sizes, int n_in,
                              void* d_out, int out_size) {
    const float* preds   = (const float*)d_in[0];
    const int*   targets = (const int*)d_in[1];
    int n = in_sizes[0];
    aucm_fused_kernel<<<NBLOCKS, THREADS>>>(preds, targets, n,
                                            (float*)d_out, out_size);
}